// round 14
// baseline (speedup 1.0000x reference)
#include <cuda_runtime.h>
#include <math.h>
#include <stdint.h>

// Problem constants (fixed: b=4, n=4096, d=1024)
#define B_BATCH 4
#define N_SEQ   4096
#define D_DIM   1024
#define M_TOK   (B_BATCH * N_SEQ)   // 16384
#define TWO_D   (2 * D_DIM)         // 2048

// Chunked scan: 64 chunks of 64 timesteps
#define NCHUNK 64
#define CLEN   64

// GEMM tiling: CTA 128x128, BK=32, 3-stage cp.async ring, XOR swizzle
#define BM 128
#define BN 128
#define BK 32
#define SSTR 32                       // floats per smem row (8 x 16B chunks)
#define ASZ (BM * SSTR)               // 4096 floats per A tile
#define STGF (2 * ASZ)                // floats per stage (A+B) = 8192
#define NSTAGE 3
#define SMEM_BYTES (NSTAGE * STGF * 4)  // 98304

// ---------------------------------------------------------------------------
// Scratch (device globals; allocation-free per harness rules)
// ---------------------------------------------------------------------------
__device__ float g_is[(size_t)M_TOK * TWO_D];    // input_state fp32 (128MB)
__device__ float g_nu[(size_t)M_TOK * D_DIM];    // sigmoid(nu) fp32 (64MB)
__device__ float g_h [(size_t)M_TOK * TWO_D];    // [h_r|h_i], tf32-rounded (128MB)
__device__ float g_xr [(size_t)M_TOK * D_DIM];   // x tf32-rounded (64MB)
__device__ float g_iwr[(size_t)TWO_D * D_DIM];   // in_w rounded
__device__ float g_nwr[(size_t)D_DIM * D_DIM];   // nu_w rounded
__device__ float g_owr[(size_t)D_DIM * TWO_D];   // out_w rounded
__device__ float2 g_A[(size_t)B_BATCH * NCHUNK * D_DIM];
__device__ float2 g_E[(size_t)B_BATCH * NCHUNK * D_DIM];
__device__ float2 g_S[(size_t)B_BATCH * NCHUNK * D_DIM];

// ---------------------------------------------------------------------------
// Helpers
// ---------------------------------------------------------------------------
__device__ __forceinline__ float f2tf32f(float x) {
    uint32_t r;
    asm volatile("cvt.rna.tf32.f32 %0, %1;" : "=r"(r) : "f"(x));
    return __uint_as_float(r);
}
__device__ __forceinline__ void mma_tf32(float c[4],
                                         uint32_t a0, uint32_t a1, uint32_t a2, uint32_t a3,
                                         uint32_t b0, uint32_t b1) {
    asm volatile(
        "mma.sync.aligned.m16n8k8.row.col.f32.tf32.tf32.f32 "
        "{%0,%1,%2,%3}, {%4,%5,%6,%7}, {%8,%9}, {%0,%1,%2,%3};"
        : "+f"(c[0]), "+f"(c[1]), "+f"(c[2]), "+f"(c[3])
        : "r"(a0), "r"(a1), "r"(a2), "r"(a3), "r"(b0), "r"(b1));
}
__device__ __forceinline__ void cp_async16(const float* smem_ptr, const float* gmem_ptr) {
    uint32_t saddr = (uint32_t)__cvta_generic_to_shared(smem_ptr);
    asm volatile("cp.async.ca.shared.global [%0], [%1], 16;" :: "r"(saddr), "l"(gmem_ptr));
}
__device__ __forceinline__ void cp_commit() { asm volatile("cp.async.commit_group;"); }
__device__ __forceinline__ void cp_wait1()  { asm volatile("cp.async.wait_group 1;"); }

// ---------------------------------------------------------------------------
// TF32 rounding pass
// ---------------------------------------------------------------------------
__global__ __launch_bounds__(256)
void round_tf32_kernel(const float* __restrict__ src, float* __restrict__ dst, int n4) {
    int i = blockIdx.x * blockDim.x + threadIdx.x;
    const int stride = gridDim.x * blockDim.x;
    for (; i < n4; i += stride) {
        float4 v = reinterpret_cast<const float4*>(src)[i];
        v.x = f2tf32f(v.x); v.y = f2tf32f(v.y);
        v.z = f2tf32f(v.z); v.w = f2tf32f(v.w);
        reinterpret_cast<float4*>(dst)[i] = v;
    }
}

// ---------------------------------------------------------------------------
// Stage loader: A tile 128x32, B tile 128x32. 256 threads: 2 threads/row,
// each loads 4 contiguous 16B chunks (gmem) into swizzled slots (smem).
// Chunk c of row r -> slot c ^ (r&7). Conflict-free stores (verified).
// ---------------------------------------------------------------------------
__device__ __forceinline__ void load_stage(const float* __restrict__ Ag,
                                           const float* __restrict__ Wg,
                                           int K, int kofs,
                                           float* __restrict__ sA,
                                           float* __restrict__ sB, int tid) {
    const int lrow = tid >> 1;          // 0..127
    const int lc   = tid & 1;           // chunk group: chunks 4lc..4lc+3
    const float* ar = Ag + (size_t)lrow * K + kofs + 16 * lc;
    const float* wr = Wg + (size_t)lrow * K + kofs + 16 * lc;
    float* sa = sA + lrow * SSTR;
    float* sb = sB + lrow * SSTR;
    const int rx = lrow & 7;
#pragma unroll
    for (int j = 0; j < 4; j++) {
        const int slot = (4 * lc + j) ^ rx;
        cp_async16(sa + 4 * slot, ar + 4 * j);
        cp_async16(sb + 4 * slot, wr + 4 * j);
    }
}

// ---------------------------------------------------------------------------
// TF32 tensor GEMM: C[M,N] = A[M,K] @ W[N,K]^T + bias[N]   (ACT=1: sigmoid)
// CTA 128x128x32, warp tile 32x64, 3-stage cp.async ring, one sync per tile.
// ---------------------------------------------------------------------------
template <int ACT>
__global__ __launch_bounds__(256, 2)
void gemm_tf32_kernel(const float* __restrict__ A,
                      const float* __restrict__ W,
                      const float* __restrict__ bias,
                      float* __restrict__ C,
                      int M, int N, int K) {
    extern __shared__ float sm[];

    const int tid    = threadIdx.x;
    const int lane   = tid & 31;
    const int warp   = tid >> 5;
    const int grp    = lane >> 2;   // 0..7
    const int tig    = lane & 3;    // 0..3
    const int warp_m = warp & 3;    // 0..3 -> 32-row slice
    const int warp_n = warp >> 2;   // 0..1 -> 64-col slice

    const int bm = blockIdx.y * BM;
    const int bn = blockIdx.x * BN;

    const float* Ag = A + (size_t)bm * K;
    const float* Wg = W + (size_t)bn * K;

    float acc[2][8][4];
#pragma unroll
    for (int i = 0; i < 2; i++)
#pragma unroll
        for (int j = 0; j < 8; j++)
#pragma unroll
            for (int v = 0; v < 4; v++) acc[i][j][v] = 0.0f;

    const int KT = K / BK;

    load_stage(Ag, Wg, K, 0,      sm,        sm + ASZ,        tid); cp_commit();
    load_stage(Ag, Wg, K, BK,     sm + STGF, sm + STGF + ASZ, tid); cp_commit();

    int s = 0;
    for (int kt = 0; kt < KT; kt++) {
        cp_wait1();          // stage kt resident
        __syncthreads();     // all warps done with the stage we're about to overwrite

        if (kt + 2 < KT) {
            int s2 = s + 2; if (s2 >= NSTAGE) s2 -= NSTAGE;
            load_stage(Ag, Wg, K, (kt + 2) * BK, sm + s2 * STGF, sm + s2 * STGF + ASZ, tid);
        }
        cp_commit();         // always commit to keep FIFO accounting exact

        const float* As = sm + s * STGF;
        const float* Bs = As + ASZ;

#pragma unroll
        for (int kk = 0; kk < 2; kk++) {   // two 16-k sub-blocks
            float4 va[2], vb[2];
#pragma unroll
            for (int mf = 0; mf < 2; mf++) {
                const int r0 = warp_m * 32 + mf * 16 + grp;
                const int r1 = r0 + 8;
                va[mf] = *reinterpret_cast<const float4*>(
                    &As[r0 * SSTR + 4 * ((4 * kk + tig) ^ (r0 & 7))]);
                vb[mf] = *reinterpret_cast<const float4*>(
                    &As[r1 * SSTR + 4 * ((4 * kk + tig) ^ (r1 & 7))]);
            }
            float4 wv[8];
#pragma unroll
            for (int nf = 0; nf < 8; nf++) {
                const int c0 = warp_n * 64 + nf * 8 + grp;
                wv[nf] = *reinterpret_cast<const float4*>(
                    &Bs[c0 * SSTR + 4 * ((4 * kk + tig) ^ (c0 & 7))]);
            }
#pragma unroll
            for (int mf = 0; mf < 2; mf++) {
                const uint32_t a00 = __float_as_uint(va[mf].x), a01 = __float_as_uint(vb[mf].x);
                const uint32_t a02 = __float_as_uint(va[mf].y), a03 = __float_as_uint(vb[mf].y);
                const uint32_t a10 = __float_as_uint(va[mf].z), a11 = __float_as_uint(vb[mf].z);
                const uint32_t a12 = __float_as_uint(va[mf].w), a13 = __float_as_uint(vb[mf].w);
#pragma unroll
                for (int nf = 0; nf < 8; nf++) {
                    mma_tf32(acc[mf][nf], a00, a01, a02, a03,
                             __float_as_uint(wv[nf].x), __float_as_uint(wv[nf].y));
                    mma_tf32(acc[mf][nf], a10, a11, a12, a13,
                             __float_as_uint(wv[nf].z), __float_as_uint(wv[nf].w));
                }
            }
        }
        s++; if (s >= NSTAGE) s = 0;
    }

    // Epilogue: bias (+sigmoid), float2 stores
#pragma unroll
    for (int mf = 0; mf < 2; mf++) {
#pragma unroll
        for (int half = 0; half < 2; half++) {
            const int row = bm + warp_m * 32 + mf * 16 + grp + half * 8;
            float* Crow = C + (size_t)row * N;
#pragma unroll
            for (int nf = 0; nf < 8; nf++) {
                const int col = bn + warp_n * 64 + nf * 8 + tig * 2;
                float v0 = acc[mf][nf][half * 2 + 0] + bias[col];
                float v1 = acc[mf][nf][half * 2 + 1] + bias[col + 1];
                if (ACT == 1) {
                    v0 = 1.0f / (1.0f + expf(-v0));
                    v1 = 1.0f / (1.0f + expf(-v1));
                }
                *reinterpret_cast<float2*>(Crow + col) = make_float2(v0, v1);
            }
        }
    }
}

// ---------------------------------------------------------------------------
// Chunked scan pass 1: per (b, chunk, j) lambda product + local end state
// ---------------------------------------------------------------------------
__global__ __launch_bounds__(256)
void scan_pass1_kernel(const float* __restrict__ theta_log,
                       const float* __restrict__ gamma_log) {
    const int gid = blockIdx.x * blockDim.x + threadIdx.x;
    if (gid >= B_BATCH * NCHUNK * D_DIM) return;
    const int j = gid & (D_DIM - 1);
    const int c = (gid >> 10) & (NCHUNK - 1);
    const int b = gid >> 16;

    const float theta = expf(theta_log[j]);
    const float ct = cosf(theta);
    const float st = sinf(theta);
    const float gm = expf(gamma_log[j]);

    size_t nu_ofs = ((size_t)b * N_SEQ + (size_t)c * CLEN) * D_DIM + j;
    size_t is_ofs = ((size_t)b * N_SEQ + (size_t)c * CLEN) * TWO_D + 2 * j;

    float Ar = 1.0f, Ai = 0.0f, Er = 0.0f, Ei = 0.0f;
#pragma unroll 4
    for (int t = 0; t < CLEN; t++) {
        const float nu = g_nu[nu_ofs];
        const float2 uv = *reinterpret_cast<const float2*>(&g_is[is_ofs]);
        const float lr = nu * ct;
        const float li = nu * st;
        const float nEr = lr * Er - li * Ei + gm * uv.x;
        const float nEi = lr * Ei + li * Er + gm * uv.y;
        const float nAr = lr * Ar - li * Ai;
        const float nAi = lr * Ai + li * Ar;
        Er = nEr; Ei = nEi; Ar = nAr; Ai = nAi;
        nu_ofs += D_DIM;
        is_ofs += TWO_D;
    }
    g_A[gid] = make_float2(Ar, Ai);
    g_E[gid] = make_float2(Er, Ei);
}

// ---------------------------------------------------------------------------
// Chunk fix-up: combine chunk summaries sequentially (per b, j)
// ---------------------------------------------------------------------------
__global__ __launch_bounds__(256)
void scan_fix_kernel() {
    const int gid = blockIdx.x * blockDim.x + threadIdx.x;
    if (gid >= B_BATCH * D_DIM) return;
    const int j = gid & (D_DIM - 1);
    const int b = gid >> 10;

    float sr = 0.0f, si = 0.0f;
#pragma unroll 4
    for (int c = 0; c < NCHUNK; c++) {
        const size_t idx = ((size_t)b * NCHUNK + c) * D_DIM + j;
        g_S[idx] = make_float2(sr, si);
        const float2 A = g_A[idx];
        const float2 E = g_E[idx];
        const float nr = A.x * sr - A.y * si + E.x;
        const float ni = A.x * si + A.y * sr + E.y;
        sr = nr; si = ni;
    }
}

// ---------------------------------------------------------------------------
// Chunked scan pass 2: re-run chunks from true start states; emit h (tf32)
// ---------------------------------------------------------------------------
__global__ __launch_bounds__(256)
void scan_pass2_kernel(const float* __restrict__ theta_log,
                       const float* __restrict__ gamma_log) {
    const int gid = blockIdx.x * blockDim.x + threadIdx.x;
    if (gid >= B_BATCH * NCHUNK * D_DIM) return;
    const int j = gid & (D_DIM - 1);
    const int c = (gid >> 10) & (NCHUNK - 1);
    const int b = gid >> 16;

    const float theta = expf(theta_log[j]);
    const float ct = cosf(theta);
    const float st = sinf(theta);
    const float gm = expf(gamma_log[j]);

    const float2 s0 = g_S[gid];
    float hr = s0.x, hi = s0.y;

    size_t nu_ofs = ((size_t)b * N_SEQ + (size_t)c * CLEN) * D_DIM + j;
    size_t is_ofs = ((size_t)b * N_SEQ + (size_t)c * CLEN) * TWO_D + 2 * j;
    size_t h_ofs  = ((size_t)b * N_SEQ + (size_t)c * CLEN) * TWO_D + j;

#pragma unroll 4
    for (int t = 0; t < CLEN; t++) {
        const float nu = g_nu[nu_ofs];
        const float2 uv = *reinterpret_cast<const float2*>(&g_is[is_ofs]);
        const float lr = nu * ct;
        const float li = nu * st;
        const float nhr = lr * hr - li * hi + gm * uv.x;
        const float nhi = lr * hi + li * hr + gm * uv.y;
        hr = nhr; hi = nhi;
        g_h[h_ofs]         = f2tf32f(hr);
        g_h[h_ofs + D_DIM] = f2tf32f(hi);
        nu_ofs += D_DIM;
        is_ofs += TWO_D;
        h_ofs  += TWO_D;
    }
}

// ---------------------------------------------------------------------------
// Launch
// ---------------------------------------------------------------------------
extern "C" void kernel_launch(void* const* d_in, const int* in_sizes, int n_in,
                              void* d_out, int out_size) {
    const float* x         = (const float*)d_in[0];
    const float* theta_log = (const float*)d_in[1];
    const float* gamma_log = (const float*)d_in[2];
    const float* nu_w      = (const float*)d_in[3];
    const float* nu_b      = (const float*)d_in[4];
    const float* in_w      = (const float*)d_in[5];
    const float* in_b      = (const float*)d_in[6];
    const float* out_w     = (const float*)d_in[7];
    const float* out_b     = (const float*)d_in[8];
    float* out = (float*)d_out;

    float *p_is, *p_nu, *p_h, *p_xr, *p_iwr, *p_nwr, *p_owr;
    cudaGetSymbolAddress((void**)&p_is,  g_is);
    cudaGetSymbolAddress((void**)&p_nu,  g_nu);
    cudaGetSymbolAddress((void**)&p_h,   g_h);
    cudaGetSymbolAddress((void**)&p_xr,  g_xr);
    cudaGetSymbolAddress((void**)&p_iwr, g_iwr);
    cudaGetSymbolAddress((void**)&p_nwr, g_nwr);
    cudaGetSymbolAddress((void**)&p_owr, g_owr);

    cudaFuncSetAttribute(gemm_tf32_kernel<0>,
                         cudaFuncAttributeMaxDynamicSharedMemorySize, SMEM_BYTES);
    cudaFuncSetAttribute(gemm_tf32_kernel<1>,
                         cudaFuncAttributeMaxDynamicSharedMemorySize, SMEM_BYTES);

    // TF32 pre-rounding: x + weights
    round_tf32_kernel<<<2048, 256>>>(x,     p_xr,  (M_TOK * D_DIM) / 4);
    round_tf32_kernel<<<512,  256>>>(in_w,  p_iwr, (TWO_D * D_DIM) / 4);
    round_tf32_kernel<<<256,  256>>>(nu_w,  p_nwr, (D_DIM * D_DIM) / 4);
    round_tf32_kernel<<<512,  256>>>(out_w, p_owr, (D_DIM * TWO_D) / 4);

    // GEMM1: input_state = x @ in_w^T + in_b   (16384 x 2048, K=1024)
    {
        dim3 grid(TWO_D / BN, M_TOK / BM);
        gemm_tf32_kernel<0><<<grid, 256, SMEM_BYTES>>>(p_xr, p_iwr, in_b, p_is,
                                                       M_TOK, TWO_D, D_DIM);
    }
    // GEMM2: nu = sigmoid(x @ nu_w^T + nu_b)   (16384 x 1024, K=1024)
    {
        dim3 grid(D_DIM / BN, M_TOK / BM);
        gemm_tf32_kernel<1><<<grid, 256, SMEM_BYTES>>>(p_xr, p_nwr, nu_b, p_nu,
                                                       M_TOK, D_DIM, D_DIM);
    }
    // Chunked parallel scan
    scan_pass1_kernel<<<(B_BATCH * NCHUNK * D_DIM) / 256, 256>>>(theta_log, gamma_log);
    scan_fix_kernel<<<(B_BATCH * D_DIM + 255) / 256, 256>>>();
    scan_pass2_kernel<<<(B_BATCH * NCHUNK * D_DIM) / 256, 256>>>(theta_log, gamma_log);
    // GEMM3: out = [h_r|h_i] @ out_w^T + out_b (16384 x 1024, K=2048)
    {
        dim3 grid(D_DIM / BN, M_TOK / BM);
        gemm_tf32_kernel<0><<<grid, 256, SMEM_BYTES>>>(p_h, p_owr, out_b, out,
                                                       M_TOK, D_DIM, TWO_D);
    }
}

// round 16
// speedup vs baseline: 1.3119x; 1.3119x over previous
#include <cuda_runtime.h>
#include <math.h>
#include <stdint.h>

// Problem constants (fixed: b=4, n=4096, d=1024)
#define B_BATCH 4
#define N_SEQ   4096
#define D_DIM   1024
#define M_TOK   (B_BATCH * N_SEQ)   // 16384
#define TWO_D   (2 * D_DIM)         // 2048

// Chunked scan: 64 chunks of 64 timesteps
#define NCHUNK 64
#define CLEN   64

// GEMM tiling: 128x128x16, 3-stage cp.async ring, XOR-swizzled smem
#define BM 128
#define BN 128
#define BK 16
#define SSTR 16
#define NSTAGE 3

// ---------------------------------------------------------------------------
// Scratch (device globals; allocation-free per harness rules)
// ---------------------------------------------------------------------------
__device__ float g_is[(size_t)M_TOK * TWO_D];    // input_state fp32 (128MB)
__device__ float g_nu[(size_t)M_TOK * D_DIM];    // sigmoid(nu) fp32 (64MB)
__device__ float g_h [(size_t)M_TOK * TWO_D];    // [h_r|h_i], tf32-rounded (128MB)
__device__ float g_xr [(size_t)M_TOK * D_DIM];   // x tf32-rounded (64MB)
__device__ float g_iwr[(size_t)TWO_D * D_DIM];   // in_w rounded
__device__ float g_nwr[(size_t)D_DIM * D_DIM];   // nu_w rounded
__device__ float g_owr[(size_t)D_DIM * TWO_D];   // out_w rounded
__device__ float2 g_A[(size_t)B_BATCH * NCHUNK * D_DIM];
__device__ float2 g_E[(size_t)B_BATCH * NCHUNK * D_DIM];
__device__ float2 g_S[(size_t)B_BATCH * NCHUNK * D_DIM];

// ---------------------------------------------------------------------------
// Helpers
// ---------------------------------------------------------------------------
__device__ __forceinline__ float f2tf32f(float x) {
    uint32_t r;
    asm volatile("cvt.rna.tf32.f32 %0, %1;" : "=r"(r) : "f"(x));
    return __uint_as_float(r);
}
__device__ __forceinline__ void mma_tf32(float c[4],
                                         uint32_t a0, uint32_t a1, uint32_t a2, uint32_t a3,
                                         uint32_t b0, uint32_t b1) {
    asm volatile(
        "mma.sync.aligned.m16n8k8.row.col.f32.tf32.tf32.f32 "
        "{%0,%1,%2,%3}, {%4,%5,%6,%7}, {%8,%9}, {%0,%1,%2,%3};"
        : "+f"(c[0]), "+f"(c[1]), "+f"(c[2]), "+f"(c[3])
        : "r"(a0), "r"(a1), "r"(a2), "r"(a3), "r"(b0), "r"(b1));
}
__device__ __forceinline__ void cp_async16(const float* smem_ptr, const float* gmem_ptr) {
    uint32_t saddr = (uint32_t)__cvta_generic_to_shared(smem_ptr);
    asm volatile("cp.async.cg.shared.global [%0], [%1], 16;" :: "r"(saddr), "l"(gmem_ptr));
}
__device__ __forceinline__ void cp_commit() { asm volatile("cp.async.commit_group;"); }
__device__ __forceinline__ void cp_wait1()  { asm volatile("cp.async.wait_group 1;"); }

// ---------------------------------------------------------------------------
// TF32 rounding pass
// ---------------------------------------------------------------------------
__global__ __launch_bounds__(256)
void round_tf32_kernel(const float* __restrict__ src, float* __restrict__ dst, int n4) {
    int i = blockIdx.x * blockDim.x + threadIdx.x;
    const int stride = gridDim.x * blockDim.x;
    for (; i < n4; i += stride) {
        float4 v = reinterpret_cast<const float4*>(src)[i];
        v.x = f2tf32f(v.x); v.y = f2tf32f(v.y);
        v.z = f2tf32f(v.z); v.w = f2tf32f(v.w);
        reinterpret_cast<float4*>(dst)[i] = v;
    }
}

// ---------------------------------------------------------------------------
// TF32 tensor GEMM: C[M,N] = A[M,K] @ W[N,K]^T + bias[N]   (ACT=1: sigmoid)
// CTA 128x128x16, warp tile 32x64, 3-stage cp.async ring, one sync per tile.
// Smem: 16B chunk c of row r stored at slot (c ^ (r&3)) -> conflict-free
// LDS.128 fragment loads AND cp.async stores. Thread tig holds k in
// {4tig..4tig+3}; MMA group 1 uses .x/.y, group 2 uses .z/.w (valid k remap).
// ---------------------------------------------------------------------------
template <int ACT>
__global__ __launch_bounds__(256)
void gemm_tf32_kernel(const float* __restrict__ A,
                      const float* __restrict__ W,
                      const float* __restrict__ bias,
                      float* __restrict__ C,
                      int M, int N, int K) {
    __shared__ float sA[NSTAGE][BM * SSTR];
    __shared__ float sB[NSTAGE][BN * SSTR];

    const int tid    = threadIdx.x;
    const int lane   = tid & 31;
    const int warp   = tid >> 5;
    const int grp    = lane >> 2;   // 0..7
    const int tig    = lane & 3;    // 0..3
    const int warp_m = warp & 3;    // 0..3 -> 32-row slice
    const int warp_n = warp >> 2;   // 0..1 -> 64-col slice

    const int bm = blockIdx.y * BM;
    const int bn = blockIdx.x * BN;

    // Loader: row = tid>>1, chunks {(tid&1), (tid&1)+2} (16B each), swizzled
    const int lrow = tid >> 1;
    const int lc   = tid & 1;
    const int sw0  = 4 * ((lc)     ^ (lrow & 3));
    const int sw1  = 4 * ((lc + 2) ^ (lrow & 3));

    const float* Ag = A + (size_t)(bm + lrow) * K + lc * 4;
    const float* Wg = W + (size_t)(bn + lrow) * K + lc * 4;

    float acc[2][8][4];
#pragma unroll
    for (int i = 0; i < 2; i++)
#pragma unroll
        for (int j = 0; j < 8; j++)
#pragma unroll
            for (int v = 0; v < 4; v++) acc[i][j][v] = 0.0f;

    const int KT = K >> 4;

    // Prologue: stages 0 and 1
#pragma unroll
    for (int p = 0; p < 2; p++) {
        const float* Ap = Ag + (size_t)p * BK;
        const float* Wp = Wg + (size_t)p * BK;
        cp_async16(&sA[p][lrow * SSTR] + sw0, Ap);
        cp_async16(&sA[p][lrow * SSTR] + sw1, Ap + 8);
        cp_async16(&sB[p][lrow * SSTR] + sw0, Wp);
        cp_async16(&sB[p][lrow * SSTR] + sw1, Wp + 8);
        cp_commit();
    }

    int s = 0;
    for (int kt = 0; kt < KT; kt++) {
        cp_wait1();          // stage kt's loads complete
        __syncthreads();     // all warps past compute kt-1 (stage s+2 reusable)

        if (kt + 2 < KT) {
            int s2 = s + 2; if (s2 >= NSTAGE) s2 -= NSTAGE;
            const float* Agn = Ag + (size_t)(kt + 2) * BK;
            const float* Wgn = Wg + (size_t)(kt + 2) * BK;
            cp_async16(&sA[s2][lrow * SSTR] + sw0, Agn);
            cp_async16(&sA[s2][lrow * SSTR] + sw1, Agn + 8);
            cp_async16(&sB[s2][lrow * SSTR] + sw0, Wgn);
            cp_async16(&sB[s2][lrow * SSTR] + sw1, Wgn + 8);
        }
        cp_commit();         // commit every iteration: FIFO accounting exact

        const float* As = &sA[s][0];
        const float* Bs = &sB[s][0];

        // 12 LDS.128 per warp per kt, conflict-free
        float4 va[2], vb[2];
#pragma unroll
        for (int mf = 0; mf < 2; mf++) {
            const int r0 = warp_m * 32 + mf * 16 + grp;
            const int r1 = r0 + 8;
            va[mf] = *reinterpret_cast<const float4*>(&As[r0 * SSTR + 4 * (tig ^ (r0 & 3))]);
            vb[mf] = *reinterpret_cast<const float4*>(&As[r1 * SSTR + 4 * (tig ^ (r1 & 3))]);
        }
        float4 wv[8];
#pragma unroll
        for (int nf = 0; nf < 8; nf++) {
            const int c0 = warp_n * 64 + nf * 8 + grp;
            wv[nf] = *reinterpret_cast<const float4*>(&Bs[c0 * SSTR + 4 * (tig ^ (c0 & 3))]);
        }

#pragma unroll
        for (int mf = 0; mf < 2; mf++) {
            const uint32_t a00 = __float_as_uint(va[mf].x), a01 = __float_as_uint(vb[mf].x);
            const uint32_t a02 = __float_as_uint(va[mf].y), a03 = __float_as_uint(vb[mf].y);
            const uint32_t a10 = __float_as_uint(va[mf].z), a11 = __float_as_uint(vb[mf].z);
            const uint32_t a12 = __float_as_uint(va[mf].w), a13 = __float_as_uint(vb[mf].w);
#pragma unroll
            for (int nf = 0; nf < 8; nf++) {
                mma_tf32(acc[mf][nf], a00, a01, a02, a03,
                         __float_as_uint(wv[nf].x), __float_as_uint(wv[nf].y));
                mma_tf32(acc[mf][nf], a10, a11, a12, a13,
                         __float_as_uint(wv[nf].z), __float_as_uint(wv[nf].w));
            }
        }
        s++; if (s >= NSTAGE) s = 0;
    }

    // Epilogue: bias (+sigmoid), float2 stores
#pragma unroll
    for (int mf = 0; mf < 2; mf++) {
#pragma unroll
        for (int half = 0; half < 2; half++) {
            const int row = bm + warp_m * 32 + mf * 16 + grp + half * 8;
            float* Crow = C + (size_t)row * N;
#pragma unroll
            for (int nf = 0; nf < 8; nf++) {
                const int col = bn + warp_n * 64 + nf * 8 + tig * 2;
                float v0 = acc[mf][nf][half * 2 + 0] + bias[col];
                float v1 = acc[mf][nf][half * 2 + 1] + bias[col + 1];
                if (ACT == 1) {
                    v0 = 1.0f / (1.0f + expf(-v0));
                    v1 = 1.0f / (1.0f + expf(-v1));
                }
                *reinterpret_cast<float2*>(Crow + col) = make_float2(v0, v1);
            }
        }
    }
}

// ---------------------------------------------------------------------------
// Chunked scan pass 1: per (b, chunk, j) lambda product + local end state
// ---------------------------------------------------------------------------
__global__ __launch_bounds__(256)
void scan_pass1_kernel(const float* __restrict__ theta_log,
                       const float* __restrict__ gamma_log) {
    const int gid = blockIdx.x * blockDim.x + threadIdx.x;
    if (gid >= B_BATCH * NCHUNK * D_DIM) return;
    const int j = gid & (D_DIM - 1);
    const int c = (gid >> 10) & (NCHUNK - 1);
    const int b = gid >> 16;

    const float theta = expf(theta_log[j]);
    const float ct = cosf(theta);
    const float st = sinf(theta);
    const float gm = expf(gamma_log[j]);

    size_t nu_ofs = ((size_t)b * N_SEQ + (size_t)c * CLEN) * D_DIM + j;
    size_t is_ofs = ((size_t)b * N_SEQ + (size_t)c * CLEN) * TWO_D + 2 * j;

    float Ar = 1.0f, Ai = 0.0f, Er = 0.0f, Ei = 0.0f;
#pragma unroll 4
    for (int t = 0; t < CLEN; t++) {
        const float nu = g_nu[nu_ofs];
        const float2 uv = *reinterpret_cast<const float2*>(&g_is[is_ofs]);
        const float lr = nu * ct;
        const float li = nu * st;
        const float nEr = lr * Er - li * Ei + gm * uv.x;
        const float nEi = lr * Ei + li * Er + gm * uv.y;
        const float nAr = lr * Ar - li * Ai;
        const float nAi = lr * Ai + li * Ar;
        Er = nEr; Ei = nEi; Ar = nAr; Ai = nAi;
        nu_ofs += D_DIM;
        is_ofs += TWO_D;
    }
    g_A[gid] = make_float2(Ar, Ai);
    g_E[gid] = make_float2(Er, Ei);
}

// ---------------------------------------------------------------------------
// Chunk fix-up: combine chunk summaries sequentially (per b, j)
// ---------------------------------------------------------------------------
__global__ __launch_bounds__(256)
void scan_fix_kernel() {
    const int gid = blockIdx.x * blockDim.x + threadIdx.x;
    if (gid >= B_BATCH * D_DIM) return;
    const int j = gid & (D_DIM - 1);
    const int b = gid >> 10;

    float sr = 0.0f, si = 0.0f;
#pragma unroll 4
    for (int c = 0; c < NCHUNK; c++) {
        const size_t idx = ((size_t)b * NCHUNK + c) * D_DIM + j;
        g_S[idx] = make_float2(sr, si);
        const float2 A = g_A[idx];
        const float2 E = g_E[idx];
        const float nr = A.x * sr - A.y * si + E.x;
        const float ni = A.x * si + A.y * sr + E.y;
        sr = nr; si = ni;
    }
}

// ---------------------------------------------------------------------------
// Chunked scan pass 2: re-run chunks from true start states; emit h (tf32)
// ---------------------------------------------------------------------------
__global__ __launch_bounds__(256)
void scan_pass2_kernel(const float* __restrict__ theta_log,
                       const float* __restrict__ gamma_log) {
    const int gid = blockIdx.x * blockDim.x + threadIdx.x;
    if (gid >= B_BATCH * NCHUNK * D_DIM) return;
    const int j = gid & (D_DIM - 1);
    const int c = (gid >> 10) & (NCHUNK - 1);
    const int b = gid >> 16;

    const float theta = expf(theta_log[j]);
    const float ct = cosf(theta);
    const float st = sinf(theta);
    const float gm = expf(gamma_log[j]);

    const float2 s0 = g_S[gid];
    float hr = s0.x, hi = s0.y;

    size_t nu_ofs = ((size_t)b * N_SEQ + (size_t)c * CLEN) * D_DIM + j;
    size_t is_ofs = ((size_t)b * N_SEQ + (size_t)c * CLEN) * TWO_D + 2 * j;
    size_t h_ofs  = ((size_t)b * N_SEQ + (size_t)c * CLEN) * TWO_D + j;

#pragma unroll 4
    for (int t = 0; t < CLEN; t++) {
        const float nu = g_nu[nu_ofs];
        const float2 uv = *reinterpret_cast<const float2*>(&g_is[is_ofs]);
        const float lr = nu * ct;
        const float li = nu * st;
        const float nhr = lr * hr - li * hi + gm * uv.x;
        const float nhi = lr * hi + li * hr + gm * uv.y;
        hr = nhr; hi = nhi;
        g_h[h_ofs]         = f2tf32f(hr);
        g_h[h_ofs + D_DIM] = f2tf32f(hi);
        nu_ofs += D_DIM;
        is_ofs += TWO_D;
        h_ofs  += TWO_D;
    }
}

// ---------------------------------------------------------------------------
// Launch
// ---------------------------------------------------------------------------
extern "C" void kernel_launch(void* const* d_in, const int* in_sizes, int n_in,
                              void* d_out, int out_size) {
    const float* x         = (const float*)d_in[0];
    const float* theta_log = (const float*)d_in[1];
    const float* gamma_log = (const float*)d_in[2];
    const float* nu_w      = (const float*)d_in[3];
    const float* nu_b      = (const float*)d_in[4];
    const float* in_w      = (const float*)d_in[5];
    const float* in_b      = (const float*)d_in[6];
    const float* out_w     = (const float*)d_in[7];
    const float* out_b     = (const float*)d_in[8];
    float* out = (float*)d_out;

    float *p_is, *p_nu, *p_h, *p_xr, *p_iwr, *p_nwr, *p_owr;
    cudaGetSymbolAddress((void**)&p_is,  g_is);
    cudaGetSymbolAddress((void**)&p_nu,  g_nu);
    cudaGetSymbolAddress((void**)&p_h,   g_h);
    cudaGetSymbolAddress((void**)&p_xr,  g_xr);
    cudaGetSymbolAddress((void**)&p_iwr, g_iwr);
    cudaGetSymbolAddress((void**)&p_nwr, g_nwr);
    cudaGetSymbolAddress((void**)&p_owr, g_owr);

    // TF32 pre-rounding: x + weights
    round_tf32_kernel<<<2048, 256>>>(x,     p_xr,  (M_TOK * D_DIM) / 4);
    round_tf32_kernel<<<512,  256>>>(in_w,  p_iwr, (TWO_D * D_DIM) / 4);
    round_tf32_kernel<<<256,  256>>>(nu_w,  p_nwr, (D_DIM * D_DIM) / 4);
    round_tf32_kernel<<<512,  256>>>(out_w, p_owr, (D_DIM * TWO_D) / 4);

    // GEMM1: input_state = x @ in_w^T + in_b   (16384 x 2048, K=1024)
    {
        dim3 grid(TWO_D / BN, M_TOK / BM);
        gemm_tf32_kernel<0><<<grid, 256>>>(p_xr, p_iwr, in_b, p_is, M_TOK, TWO_D, D_DIM);
    }
    // GEMM2: nu = sigmoid(x @ nu_w^T + nu_b)   (16384 x 1024, K=1024)
    {
        dim3 grid(D_DIM / BN, M_TOK / BM);
        gemm_tf32_kernel<1><<<grid, 256>>>(p_xr, p_nwr, nu_b, p_nu, M_TOK, D_DIM, D_DIM);
    }
    // Chunked parallel scan
    scan_pass1_kernel<<<(B_BATCH * NCHUNK * D_DIM) / 256, 256>>>(theta_log, gamma_log);
    scan_fix_kernel<<<(B_BATCH * D_DIM + 255) / 256, 256>>>();
    scan_pass2_kernel<<<(B_BATCH * NCHUNK * D_DIM) / 256, 256>>>(theta_log, gamma_log);
    // GEMM3: out = [h_r|h_i] @ out_w^T + out_b (16384 x 1024, K=2048)
    {
        dim3 grid(D_DIM / BN, M_TOK / BM);
        gemm_tf32_kernel<0><<<grid, 256>>>(p_h, p_owr, out_b, out, M_TOK, D_DIM, TWO_D);
    }
}